// round 11
// baseline (speedup 1.0000x reference)
#include <cuda_runtime.h>
#include <stdint.h>

#define BB 128
#define TT 1024
#define DD 256
#define UU 48
#define NG 256   // groups of 4 steps: t = 4g+1 .. 4g+4

// Scratch (allocation-free rule: __device__ globals)
__device__ float         g_logits[(size_t)BB * TT * UU];     // 25.2 MB
__device__ unsigned char g_bp[(size_t)(TT - 1) * BB * UU];   // 6.29 MB
__device__ int           g_last[BB];

#define ADD_F32X2(out, a, b) \
    asm("add.rn.f32x2 %0, %1, %2;" : "=l"(out) : "l"(a), "l"(b))

// ---------------------------------------------------------------------------
// Kernel 1: logits = x @ kernel + bias (measured ~106us ~ 1.12x fp32 floor)
// ---------------------------------------------------------------------------
#define GR 128
#define GK 64
#define XPAD 130

__global__ __launch_bounds__(128) void gemm_kernel(const float* __restrict__ x,
                                                   const float* __restrict__ w,
                                                   const float* __restrict__ bias) {
    __shared__ float xs[GK][XPAD];
    __shared__ float ws[GK][UU];

    const int tid = threadIdx.x;
    const int tc  = tid & 3;
    const int tr  = tid >> 2;
    const size_t row0 = (size_t)blockIdx.x * GR;

    float acc[4][12];
#pragma unroll
    for (int i = 0; i < 4; i++)
#pragma unroll
        for (int j = 0; j < 12; j++) acc[i][j] = 0.0f;

    for (int kc = 0; kc < DD; kc += GK) {
        const float4* wg = (const float4*)(w + (size_t)kc * UU);
        float4* wsv = (float4*)&ws[0][0];
#pragma unroll
        for (int i = 0; i < 6; i++) wsv[tid + i * 128] = wg[tid + i * 128];

#pragma unroll
        for (int i = 0; i < 16; i++) {
            int j  = tid + i * 128;
            int r  = j >> 4;
            int k4 = j & 15;
            float4 f = *(const float4*)(x + (row0 + (size_t)r) * DD + kc + k4 * 4);
            xs[k4 * 4 + 0][r] = f.x;
            xs[k4 * 4 + 1][r] = f.y;
            xs[k4 * 4 + 2][r] = f.z;
            xs[k4 * 4 + 3][r] = f.w;
        }
        __syncthreads();

#pragma unroll 4
        for (int k = 0; k < GK; k++) {
            float xv[4], wv[12];
            float2 xa = *(const float2*)&xs[k][tr * 4];
            float2 xb = *(const float2*)&xs[k][tr * 4 + 2];
            xv[0] = xa.x; xv[1] = xa.y; xv[2] = xb.x; xv[3] = xb.y;
#pragma unroll
            for (int q = 0; q < 3; q++) {
                float4 wq = *(const float4*)&ws[k][tc * 12 + q * 4];
                wv[q * 4 + 0] = wq.x; wv[q * 4 + 1] = wq.y;
                wv[q * 4 + 2] = wq.z; wv[q * 4 + 3] = wq.w;
            }
#pragma unroll
            for (int i = 0; i < 4; i++)
#pragma unroll
                for (int j = 0; j < 12; j++) acc[i][j] += xv[i] * wv[j];
        }
        __syncthreads();
    }

    float bv[12];
#pragma unroll
    for (int j = 0; j < 12; j++) bv[j] = bias[tc * 12 + j];

#pragma unroll
    for (int i = 0; i < 4; i++) {
        size_t r = row0 + tr * 4 + i;
        float* o = g_logits + r * UU + tc * 12;
#pragma unroll
        for (int j = 0; j < 12; j++) o[j] = acc[i][j] + bv[j];
    }
}

// ---------------------------------------------------------------------------
// Step bodies (identical math to the R10 passing kernel).
// ---------------------------------------------------------------------------
__device__ __forceinline__ void value_step(const unsigned long long (&trv)[24],
                                           const float* __restrict__ stp,
                                           float* __restrict__ stn,
                                           int lu, bool act, float cur) {
    float v[24];
#pragma unroll
    for (int m = 0; m < 12; m++) {
        ulonglong2 s = *(const ulonglong2*)&stp[4 * m];
        unsigned long long ca, cb;
        ADD_F32X2(ca, s.x, trv[2 * m + 0]);
        ADD_F32X2(cb, s.y, trv[2 * m + 1]);
        float a0 = __uint_as_float((unsigned)(ca & 0xFFFFFFFFull));
        float a1 = __uint_as_float((unsigned)(ca >> 32));
        float b0 = __uint_as_float((unsigned)(cb & 0xFFFFFFFFull));
        float b1 = __uint_as_float((unsigned)(cb >> 32));
        v[2 * m + 0] = fmaxf(a0, a1);
        v[2 * m + 1] = fmaxf(b0, b1);
    }
#pragma unroll
    for (int j = 0; j < 12; j++) v[j] = fmaxf(v[2 * j], v[2 * j + 1]);
#pragma unroll
    for (int j = 0; j < 6; j++)  v[j] = fmaxf(v[2 * j], v[2 * j + 1]);
#pragma unroll
    for (int j = 0; j < 3; j++)  v[j] = fmaxf(v[2 * j], v[2 * j + 1]);
    float bv = fmaxf(fmaxf(v[0], v[1]), v[2]);
    if (act) stn[lu] = cur + bv;
}

// argmax over 48 candidates, first-index tie-break (strict-greater
// replacement, slots ascend with candidate index) — matches jnp.argmax.
__device__ __forceinline__ void index_step(const unsigned long long (&trv)[24],
                                           const float* __restrict__ stp,
                                           bool act, unsigned char* dst) {
    float v[24];
    int   ix[24];
#pragma unroll
    for (int m = 0; m < 12; m++) {
        ulonglong2 s = *(const ulonglong2*)&stp[4 * m];
        unsigned long long ca, cb;
        ADD_F32X2(ca, s.x, trv[2 * m + 0]);
        ADD_F32X2(cb, s.y, trv[2 * m + 1]);
        float a0 = __uint_as_float((unsigned)(ca & 0xFFFFFFFFull));
        float a1 = __uint_as_float((unsigned)(ca >> 32));
        float b0 = __uint_as_float((unsigned)(cb & 0xFFFFFFFFull));
        float b1 = __uint_as_float((unsigned)(cb >> 32));
        v[2 * m + 0]  = fmaxf(a0, a1);
        ix[2 * m + 0] = (a1 > a0) ? (4 * m + 1) : (4 * m + 0);
        v[2 * m + 1]  = fmaxf(b0, b1);
        ix[2 * m + 1] = (b1 > b0) ? (4 * m + 3) : (4 * m + 2);
    }
#pragma unroll
    for (int j = 0; j < 12; j++) {
        bool g = v[2 * j + 1] > v[2 * j];
        v[j]  = fmaxf(v[2 * j], v[2 * j + 1]);
        ix[j] = g ? ix[2 * j + 1] : ix[2 * j];
    }
#pragma unroll
    for (int j = 0; j < 6; j++) {
        bool g = v[2 * j + 1] > v[2 * j];
        v[j]  = fmaxf(v[2 * j], v[2 * j + 1]);
        ix[j] = g ? ix[2 * j + 1] : ix[2 * j];
    }
#pragma unroll
    for (int j = 0; j < 3; j++) {
        bool g = v[2 * j + 1] > v[2 * j];
        v[j]  = fmaxf(v[2 * j], v[2 * j + 1]);
        ix[j] = g ? ix[2 * j + 1] : ix[2 * j];
    }
    float m01 = fmaxf(v[0], v[1]);
    int  i01  = (v[1] > v[0]) ? ix[1] : ix[0];
    int  bi   = (v[2] > m01) ? ix[2] : i01;
    if (act) *dst = (unsigned char)bi;
}

// ---------------------------------------------------------------------------
// Kernel 2: Viterbi forward as a producer/consumer pipeline.
// 256 threads / 8 warps:
//   warps 0-1 (tid 0-63):    PRODUCER (value recurrence), SMSP 0-1 exclusive.
//   warps 2-3 (tid 64-127):  consumer pair A (even groups), SMSP 2-3.
//   warps 4-5 (tid 128-191): exit immediately (keeps pair B off SMSP 0-1).
//   warps 6-7 (tid 192-255): consumer pair B (odd groups), SMSP 2-3.
// State ring: st[16][UU], slot = t & 15 (4 groups deep).
// Named barriers: FULL id 1+(g&3) (producer arrives after group g; consumer
// of group g syncs). EMPTY id 5+(g&3) (consumer arrives after group g;
// producer syncs before group g+3 — group g+3's writes first touch consumer
// g's read set at slot 4g+16 == 4g). Producer internal per-step sync:
// bar.sync 9,64. bar.sync drains STS (HW fence), so no membar needed.
// ---------------------------------------------------------------------------
__global__ __launch_bounds__(256) void viterbi_fwd(const float* __restrict__ trans) {
    const int b   = blockIdx.x;
    const int tid = threadIdx.x;
    const int wid = tid >> 5;

    __shared__ __align__(16) float st[16][UU];

    const bool is_prod = (wid < 2);
    const bool is_dead = (wid == 4 || wid == 5);
    const int  pair    = (wid >= 6) ? 1 : 0;          // consumer pair id
    const int  lu      = is_prod ? tid : (pair ? (tid - 192) : (tid - 64));
    const bool act     = !is_dead && (lu < UU);
    const int  u       = (act ? lu : (UU - 1));

    unsigned long long trv[24];
    if (!is_dead) {
#pragma unroll
        for (int j = 0; j < 24; j++) {
            unsigned lo = __float_as_uint(trans[(2 * j) * UU + u]);
            unsigned hi = __float_as_uint(trans[(2 * j + 1) * UU + u]);
            trv[j] = (unsigned long long)lo | ((unsigned long long)hi << 32);
        }
    }

    const float* lg = g_logits + (size_t)b * TT * UU + u;
    float fb[4];
    if (is_prod) {
        if (act) st[0][lu] = lg[0];
        fb[0] = lg[(size_t)1 * UU];
        fb[1] = lg[(size_t)2 * UU];
        fb[2] = lg[(size_t)3 * UU];
        fb[3] = lg[(size_t)4 * UU];
    }
    unsigned char* bpb = g_bp + (size_t)b * UU + u;

    __syncthreads();
    if (is_dead) return;

    if (is_prod) {
        // ---------------- PRODUCER ----------------
        for (int g = 0; g < NG; ++g) {
            if (g >= 3) {
                int eid = 5 + ((g - 3) & 3);
                asm volatile("bar.sync %0, 128;" :: "r"(eid) : "memory");
            }
#pragma unroll
            for (int q = 0; q < 4; ++q) {
                int t = 4 * g + q + 1;
                if (t < TT) {
                    float cur = fb[q];
                    int tn = t + 4;
                    if (tn > TT - 1) tn = TT - 1;
                    fb[q] = lg[(size_t)tn * UU];      // consumed 4 steps later
                    value_step(trv, st[(t - 1) & 15], st[t & 15], lu, act, cur);
                    asm volatile("bar.sync 9, 64;" ::: "memory");
                }
            }
            int fid = 1 + (g & 3);
            asm volatile("bar.arrive %0, 128;" :: "r"(fid) : "memory");
        }
        // final state lives in st[(TT-1) & 15] = st[15]
        if (tid == 0) {
            float bv = st[15][0];
            int bi = 0;
#pragma unroll
            for (int i = 1; i < UU; i++) {
                if (st[15][i] > bv) { bv = st[15][i]; bi = i; }
            }
            g_last[b] = bi;
        }
    } else {
        // ---------------- CONSUMERS ----------------
        for (int g = pair; g < NG; g += 2) {
            int fid = 1 + (g & 3);
            asm volatile("bar.sync %0, 128;" :: "r"(fid) : "memory");
#pragma unroll
            for (int q = 0; q < 4; ++q) {
                int t = 4 * g + q + 1;
                if (t < TT) {
                    index_step(trv, st[(t - 1) & 15], act,
                               bpb + (size_t)(t - 1) * BB * UU);
                }
            }
            int eid = 5 + (g & 3);
            asm volatile("bar.arrive %0, 128;" :: "r"(eid) : "memory");
        }
    }
}

// ---------------------------------------------------------------------------
// Kernel 3: backtrack + emit (measured 29.5us). 128 blocks, 256 threads.
// ---------------------------------------------------------------------------
__global__ __launch_bounds__(256) void backtrack_kernel(float* __restrict__ out) {
    __shared__ unsigned char sbp[(TT - 1) * UU];  // 49104 B

    const int b = blockIdx.x;
    const int tid = threadIdx.x;

    const unsigned char* gsrc = g_bp + (size_t)b * UU;
    for (int idx = tid; idx < (TT - 1) * 3; idx += 256) {
        int s = idx / 3;
        int w = idx % 3;
        uint4 v = *(const uint4*)(gsrc + (size_t)s * BB * UU + w * 16);
        *(uint4*)(sbp + s * UU + w * 16) = v;
    }
    __syncthreads();

    if (tid != 0) return;

    int tag = g_last[b];
    float* ob = out + (size_t)b * TT;
    ob[TT - 1] = (float)tag;

    int off = (TT - 2) * UU;
#pragma unroll 8
    for (int s = TT - 2; s >= 0; --s) {
        tag = sbp[off + tag];
        ob[s] = (float)tag;
        off -= UU;
    }
}

// ---------------------------------------------------------------------------
extern "C" void kernel_launch(void* const* d_in, const int* in_sizes, int n_in,
                              void* d_out, int out_size) {
    const float* x     = (const float*)d_in[0];  // (128,1024,256)
    const float* kern  = (const float*)d_in[1];  // (256,48)
    const float* bias  = (const float*)d_in[2];  // (48,)
    const float* chain = (const float*)d_in[3];  // (48,48)
    float* out = (float*)d_out;                  // (128,1024) float32

    gemm_kernel<<<(BB * TT) / GR, 128>>>(x, kern, bias);
    viterbi_fwd<<<BB, 256>>>(chain);
    backtrack_kernel<<<BB, 256>>>(out);
}

// round 12
// speedup vs baseline: 1.0649x; 1.0649x over previous
#include <cuda_runtime.h>
#include <stdint.h>

#define BB 128
#define TT 1024
#define DD 256
#define UU 48

// Scratch (allocation-free rule: __device__ globals)
__device__ float         g_logits[(size_t)BB * TT * UU];     // 25.2 MB
__device__ unsigned char g_bp[(size_t)(TT - 1) * BB * UU];   // 6.29 MB
__device__ int           g_last[BB];

#define ADD_F32X2(out, a, b) \
    asm("add.rn.f32x2 %0, %1, %2;" : "=l"(out) : "l"(a), "l"(b))

// ---------------------------------------------------------------------------
// Kernel 1: logits = x @ kernel + bias (measured ~106us ~ 1.12x fp32 floor)
// ---------------------------------------------------------------------------
#define GR 128
#define GK 64
#define XPAD 130

__global__ __launch_bounds__(128) void gemm_kernel(const float* __restrict__ x,
                                                   const float* __restrict__ w,
                                                   const float* __restrict__ bias) {
    __shared__ float xs[GK][XPAD];
    __shared__ float ws[GK][UU];

    const int tid = threadIdx.x;
    const int tc  = tid & 3;
    const int tr  = tid >> 2;
    const size_t row0 = (size_t)blockIdx.x * GR;

    float acc[4][12];
#pragma unroll
    for (int i = 0; i < 4; i++)
#pragma unroll
        for (int j = 0; j < 12; j++) acc[i][j] = 0.0f;

    for (int kc = 0; kc < DD; kc += GK) {
        const float4* wg = (const float4*)(w + (size_t)kc * UU);
        float4* wsv = (float4*)&ws[0][0];
#pragma unroll
        for (int i = 0; i < 6; i++) wsv[tid + i * 128] = wg[tid + i * 128];

#pragma unroll
        for (int i = 0; i < 16; i++) {
            int j  = tid + i * 128;
            int r  = j >> 4;
            int k4 = j & 15;
            float4 f = *(const float4*)(x + (row0 + (size_t)r) * DD + kc + k4 * 4);
            xs[k4 * 4 + 0][r] = f.x;
            xs[k4 * 4 + 1][r] = f.y;
            xs[k4 * 4 + 2][r] = f.z;
            xs[k4 * 4 + 3][r] = f.w;
        }
        __syncthreads();

#pragma unroll 4
        for (int k = 0; k < GK; k++) {
            float xv[4], wv[12];
            float2 xa = *(const float2*)&xs[k][tr * 4];
            float2 xb = *(const float2*)&xs[k][tr * 4 + 2];
            xv[0] = xa.x; xv[1] = xa.y; xv[2] = xb.x; xv[3] = xb.y;
#pragma unroll
            for (int q = 0; q < 3; q++) {
                float4 wq = *(const float4*)&ws[k][tc * 12 + q * 4];
                wv[q * 4 + 0] = wq.x; wv[q * 4 + 1] = wq.y;
                wv[q * 4 + 2] = wq.z; wv[q * 4 + 3] = wq.w;
            }
#pragma unroll
            for (int i = 0; i < 4; i++)
#pragma unroll
                for (int j = 0; j < 12; j++) acc[i][j] += xv[i] * wv[j];
        }
        __syncthreads();
    }

    float bv[12];
#pragma unroll
    for (int j = 0; j < 12; j++) bv[j] = bias[tc * 12 + j];

#pragma unroll
    for (int i = 0; i < 4; i++) {
        size_t r = row0 + tr * 4 + i;
        float* o = g_logits + r * UU + tc * 12;
#pragma unroll
        for (int j = 0; j < 12; j++) o[j] = acc[i][j] + bv[j];
    }
}

// ---------------------------------------------------------------------------
// Value step: max over all 48 candidates, pure-fmaxf tree (R10, rel_err 0).
// ---------------------------------------------------------------------------
__device__ __forceinline__ void value_step(const unsigned long long (&trv)[24],
                                           const float* __restrict__ stp,
                                           float* __restrict__ stn,
                                           int lu, bool act, float cur) {
    float v[24];
#pragma unroll
    for (int m = 0; m < 12; m++) {
        ulonglong2 s = *(const ulonglong2*)&stp[4 * m];
        unsigned long long ca, cb;
        ADD_F32X2(ca, s.x, trv[2 * m + 0]);
        ADD_F32X2(cb, s.y, trv[2 * m + 1]);
        float a0 = __uint_as_float((unsigned)(ca & 0xFFFFFFFFull));
        float a1 = __uint_as_float((unsigned)(ca >> 32));
        float b0 = __uint_as_float((unsigned)(cb & 0xFFFFFFFFull));
        float b1 = __uint_as_float((unsigned)(cb >> 32));
        v[2 * m + 0] = fmaxf(a0, a1);
        v[2 * m + 1] = fmaxf(b0, b1);
    }
#pragma unroll
    for (int j = 0; j < 12; j++) v[j] = fmaxf(v[2 * j], v[2 * j + 1]);
#pragma unroll
    for (int j = 0; j < 6; j++)  v[j] = fmaxf(v[2 * j], v[2 * j + 1]);
#pragma unroll
    for (int j = 0; j < 3; j++)  v[j] = fmaxf(v[2 * j], v[2 * j + 1]);
    float bv = fmaxf(fmaxf(v[0], v[1]), v[2]);
    if (act) stn[lu] = cur + bv;
}

// ---------------------------------------------------------------------------
// Index half-step: argmax over 24 candidates [base, base+24), first-index
// tie-break (strict-greater, ascending-index slots). Returns local (val,idx).
// ---------------------------------------------------------------------------
__device__ __forceinline__ void index24(const unsigned long long (&tri)[12],
                                        const float* __restrict__ stp,
                                        int base, float& bvo, int& bio) {
    float v[12];
    int   ix[12];
#pragma unroll
    for (int m = 0; m < 6; m++) {
        ulonglong2 s = *(const ulonglong2*)&stp[base + 4 * m];
        unsigned long long ca, cb;
        ADD_F32X2(ca, s.x, tri[2 * m + 0]);
        ADD_F32X2(cb, s.y, tri[2 * m + 1]);
        float a0 = __uint_as_float((unsigned)(ca & 0xFFFFFFFFull));
        float a1 = __uint_as_float((unsigned)(ca >> 32));
        float b0 = __uint_as_float((unsigned)(cb & 0xFFFFFFFFull));
        float b1 = __uint_as_float((unsigned)(cb >> 32));
        v[2 * m + 0]  = fmaxf(a0, a1);
        ix[2 * m + 0] = (a1 > a0) ? (4 * m + 1) : (4 * m + 0);
        v[2 * m + 1]  = fmaxf(b0, b1);
        ix[2 * m + 1] = (b1 > b0) ? (4 * m + 3) : (4 * m + 2);
    }
#pragma unroll
    for (int j = 0; j < 6; j++) {
        bool g = v[2 * j + 1] > v[2 * j];
        v[j]  = fmaxf(v[2 * j], v[2 * j + 1]);
        ix[j] = g ? ix[2 * j + 1] : ix[2 * j];
    }
#pragma unroll
    for (int j = 0; j < 3; j++) {
        bool g = v[2 * j + 1] > v[2 * j];
        v[j]  = fmaxf(v[2 * j], v[2 * j + 1]);
        ix[j] = g ? ix[2 * j + 1] : ix[2 * j];
    }
    float m01 = fmaxf(v[0], v[1]);
    int  i01  = (v[1] > v[0]) ? ix[1] : ix[0];
    bvo = fmaxf(m01, v[2]);
    bio = ((v[2] > m01) ? ix[2] : i01) + base;
}

// ---------------------------------------------------------------------------
// Kernel 2: Viterbi forward. 160 threads / 5 warps, R10 lockstep + prefetch:
//   warps 0-1 (tid 0-63, 48 active): VALUE recurrence (~70 instr).
//   warps 2-4 (tid 64-159, 96 threads): INDEX, 2 threads/output
//     (u = (tid-64)>>1, h = (tid-64)&1, 24 candidates each ~80 instr),
//     halves combined via shfl.down 1 (high half wins only on strict >).
// Warp->SMSP: w4 shares SMSP0 with value-w0; interleaving hides rt=2.
// t-loop unrolled x4 with statically-indexed prefetch regs (R10 fix).
// ---------------------------------------------------------------------------
__global__ __launch_bounds__(160) void viterbi_fwd(const float* __restrict__ trans) {
    const int b   = blockIdx.x;
    const int tid = threadIdx.x;

    __shared__ __align__(16) float st[2][UU];

    const bool is_val = (tid < 64);
    const int  it     = tid - 64;                       // index-thread id
    const int  lu     = is_val ? tid : (it >> 1);
    const int  h      = is_val ? 0 : (it & 1);
    const bool act    = (lu < UU);
    const int  u      = act ? lu : (UU - 1);
    const int  base   = 24 * h;

    // value threads: full trans column (24 x f32x2); index threads: half (12)
    unsigned long long trv[24];
    unsigned long long tri[12];
    if (is_val) {
#pragma unroll
        for (int j = 0; j < 24; j++) {
            unsigned lo = __float_as_uint(trans[(2 * j) * UU + u]);
            unsigned hi = __float_as_uint(trans[(2 * j + 1) * UU + u]);
            trv[j] = (unsigned long long)lo | ((unsigned long long)hi << 32);
        }
    } else {
#pragma unroll
        for (int j = 0; j < 12; j++) {
            unsigned lo = __float_as_uint(trans[(base + 2 * j) * UU + u]);
            unsigned hi = __float_as_uint(trans[(base + 2 * j + 1) * UU + u]);
            tri[j] = (unsigned long long)lo | ((unsigned long long)hi << 32);
        }
    }

    const float* lg = g_logits + (size_t)b * TT * UU + u;
    float fb[4];
    if (is_val) {
        if (act) st[0][lu] = lg[0];
        fb[0] = lg[(size_t)1 * UU];
        fb[1] = lg[(size_t)2 * UU];
        fb[2] = lg[(size_t)3 * UU];
        fb[3] = lg[(size_t)4 * UU];
    }
    unsigned char* bpb = g_bp + (size_t)b * UU + u;

    __syncthreads();

    int p = 0;
    int tb = 1;
    for (; tb + 3 < TT; tb += 4) {
#pragma unroll
        for (int q = 0; q < 4; q++) {
            const int t = tb + q;
            if (is_val) {
                float cur = fb[q];
                int tn = t + 4;
                if (tn > TT - 1) tn = TT - 1;
                fb[q] = lg[(size_t)tn * UU];     // consumed 4 steps later
                value_step(trv, st[p], st[p ^ 1], lu, act, cur);
            } else {
                float bv; int bi;
                index24(tri, st[p], base, bv, bi);
                float ov = __shfl_down_sync(0xFFFFFFFFu, bv, 1);
                int   oi = __shfl_down_sync(0xFFFFFFFFu, bi, 1);
                int   mi = (ov > bv) ? oi : bi;   // high half strictly greater
                if (h == 0) bpb[(size_t)(t - 1) * BB * UU] = (unsigned char)mi;
            }
            __syncthreads();
            p ^= 1;
        }
    }
    // epilogue: t = tb .. TT-1 (3 steps; fb[0..2] already hold their logits)
#pragma unroll
    for (int q = 0; q < 3; q++) {
        const int t = tb + q;
        if (t < TT) {
            if (is_val) {
                value_step(trv, st[p], st[p ^ 1], lu, act, fb[q]);
            } else {
                float bv; int bi;
                index24(tri, st[p], base, bv, bi);
                float ov = __shfl_down_sync(0xFFFFFFFFu, bv, 1);
                int   oi = __shfl_down_sync(0xFFFFFFFFu, bi, 1);
                int   mi = (ov > bv) ? oi : bi;
                if (h == 0) bpb[(size_t)(t - 1) * BB * UU] = (unsigned char)mi;
            }
            __syncthreads();
            p ^= 1;
        }
    }

    if (tid == 0) {
        float bv = st[p][0];
        int bi = 0;
#pragma unroll
        for (int i = 1; i < UU; i++) {
            if (st[p][i] > bv) { bv = st[p][i]; bi = i; }
        }
        g_last[b] = bi;
    }
}

// ---------------------------------------------------------------------------
// Kernel 3: backtrack + emit (measured 29.5us). 128 blocks, 256 threads.
// ---------------------------------------------------------------------------
__global__ __launch_bounds__(256) void backtrack_kernel(float* __restrict__ out) {
    __shared__ unsigned char sbp[(TT - 1) * UU];  // 49104 B

    const int b = blockIdx.x;
    const int tid = threadIdx.x;

    const unsigned char* gsrc = g_bp + (size_t)b * UU;
    for (int idx = tid; idx < (TT - 1) * 3; idx += 256) {
        int s = idx / 3;
        int w = idx % 3;
        uint4 v = *(const uint4*)(gsrc + (size_t)s * BB * UU + w * 16);
        *(uint4*)(sbp + s * UU + w * 16) = v;
    }
    __syncthreads();

    if (tid != 0) return;

    int tag = g_last[b];
    float* ob = out + (size_t)b * TT;
    ob[TT - 1] = (float)tag;

    int off = (TT - 2) * UU;
#pragma unroll 8
    for (int s = TT - 2; s >= 0; --s) {
        tag = sbp[off + tag];
        ob[s] = (float)tag;
        off -= UU;
    }
}

// ---------------------------------------------------------------------------
extern "C" void kernel_launch(void* const* d_in, const int* in_sizes, int n_in,
                              void* d_out, int out_size) {
    const float* x     = (const float*)d_in[0];  // (128,1024,256)
    const float* kern  = (const float*)d_in[1];  // (256,48)
    const float* bias  = (const float*)d_in[2];  // (48,)
    const float* chain = (const float*)d_in[3];  // (48,48)
    float* out = (float*)d_out;                  // (128,1024) float32

    gemm_kernel<<<(BB * TT) / GR, 128>>>(x, kern, bias);
    viterbi_fwd<<<BB, 160>>>(chain);
    backtrack_kernel<<<BB, 256>>>(out);
}